// round 1
// baseline (speedup 1.0000x reference)
#include <cuda_runtime.h>
#include <cstdint>

// map_h[b,h,s,e] = max(x[b,h,s..e]) on the filled diagonals, 0 elsewhere.
// Fill predicate for N=64, NUM_SCALE_LAYERS=[16,8,8]:
//   d = e-s
//   d in [0,15]                      -> filled for all s
//   d in {17,19,...,31} (odd)        -> filled for s even
//   d in {35,39,...,63} (d%4==3... i.e. (d-35)%4==0) -> filled for s%4==0
__device__ __forceinline__ bool is_filled(int s, int e) {
    int d = e - s;
    if (d < 0)  return false;
    if (d <= 15) return true;
    if (d == 16) return false;
    if (d <= 31) return ((d & 1) != 0) && ((s & 1) == 0);
    if (d < 35)  return false;
    return (((d - 35) & 3) == 0) && ((s & 3) == 0);
}

// Block: 256 threads, handles 16 consecutive (b,h) rows.
// Thread t: row-local rl = t>>4, e-group eg = t&15 (columns 4*eg .. 4*eg+3).
__global__ __launch_bounds__(256, 8)
void sparseprop_kernel(const float* __restrict__ x,
                       float* __restrict__ out,
                       int B, int H) {
    const int N = 64;
    __shared__ float sx[16 * 64];

    const int row0 = blockIdx.x * 16;
    const int t  = threadIdx.x;
    const int rl = t >> 4;
    const int eg = t & 15;
    const int row = row0 + rl;          // global (b*H + h)

    // Cooperative load: 16 rows x 64 floats = 256 float4, one per thread.
    reinterpret_cast<float4*>(sx)[t] =
        reinterpret_cast<const float4*>(x + (size_t)row0 * N)[t];
    __syncthreads();

    const float* xr = &sx[rl * 64];

    const int e0 = 4 * eg;
    const int e1 = e0 + 1, e2 = e0 + 2, e3 = e0 + 3;
    const float NEG = -3.402823466e+38f;
    float m0 = NEG, m1 = NEG, m2 = NEG, m3 = NEG;

    float4* orow = reinterpret_cast<float4*>(out + (size_t)row * (N * N));

    const int h = row & (H - 1);        // H=512 (power of two)
    const int b = row >> 9;             // row / 512
    const bool do_mask = (h == 0);
    float4* mrow = reinterpret_cast<float4*>(
        out + (size_t)B * H * N * N + (size_t)b * (N * N));

    #pragma unroll 4
    for (int s = N - 1; s >= 0; --s) {
        const float xs = xr[s];
        if (s <= e3) {
            m3 = fmaxf(m3, xs);
            if (s <= e2) {
                m2 = fmaxf(m2, xs);
                if (s <= e1) {
                    m1 = fmaxf(m1, xs);
                    if (s <= e0) m0 = fmaxf(m0, xs);
                }
            }
        }
        const bool f0 = is_filled(s, e0);
        const bool f1 = is_filled(s, e1);
        const bool f2 = is_filled(s, e2);
        const bool f3 = is_filled(s, e3);

        float4 w;
        w.x = f0 ? m0 : 0.0f;
        w.y = f1 ? m1 : 0.0f;
        w.z = f2 ? m2 : 0.0f;
        w.w = f3 ? m3 : 0.0f;
        orow[s * 16 + eg] = w;

        if (do_mask) {
            float4 mk;
            mk.x = f0 ? 1.0f : 0.0f;
            mk.y = f1 ? 1.0f : 0.0f;
            mk.z = f2 ? 1.0f : 0.0f;
            mk.w = f3 ? 1.0f : 0.0f;
            mrow[s * 16 + eg] = mk;
        }
    }
}

extern "C" void kernel_launch(void* const* d_in, const int* in_sizes, int n_in,
                              void* d_out, int out_size) {
    const float* x = (const float*)d_in[0];
    float* out = (float*)d_out;

    const int N = 64;
    const int H = 512;
    const int total = in_sizes[0];          // B*H*N
    const int B = total / (H * N);          // 32

    const int rows = B * H;                 // 16384
    const int blocks = rows / 16;           // 1024

    sparseprop_kernel<<<blocks, 256>>>(x, out, B, H);
}

// round 2
// speedup vs baseline: 1.1338x; 1.1338x over previous
#include <cuda_runtime.h>
#include <cstdint>

// map_h[b,h,s,e] = max(x[b,h,s..e]) where filled, else 0.
// Fill predicate (N=64, layers [16,8,8]), d = e-s:
//   d in [0,15]                           : all s
//   d odd in [17,31]                      : s even   (implies e odd)
//   d in {35,39,...,63} (d%4==3)          : s%4==0   (implies e%4==3)
// Per thread, e0..e3 = 4*eg..4*eg+3, so:
//   region2 can only fire for e1,e3 (odd); region3 only for e3 (==3 mod 4).
// Fully unrolling s in steps of 4 fixes s%4 per slot -> each test is one
// unsigned range check against a per-thread constant.

__global__ __launch_bounds__(256)
void sparseprop_kernel(const float* __restrict__ x,
                       float* __restrict__ out,
                       int B, int H) {
    const int N = 64;
    __shared__ float sx[16 * 64];

    const int row0 = blockIdx.x * 16;
    const int t  = threadIdx.x;
    const int rl = t >> 4;
    const int eg = t & 15;
    const int row = row0 + rl;            // global (b*H + h)

    // Cooperative load: 16 rows x 64 floats = 256 float4.
    reinterpret_cast<float4*>(sx)[t] =
        reinterpret_cast<const float4*>(x + (size_t)row0 * N)[t];
    __syncthreads();

    const float* xr = &sx[rl * 64];

    const int e0 = 4 * eg;
    const int e1 = e0 + 1, e2 = e0 + 2, e3 = e0 + 3;

    // Range-test bases (may be negative; unsigned wrap makes test false for s<lo).
    const int r1a = e0 - 15, r1b = e1 - 15, r1c = e2 - 15, r1d = e3 - 15;
    const int r2b = e1 - 31;   // region2 for e1: s in [e1-31, e1-17], s even
    const int r2d = e3 - 31;   // region2 for e3
    const int r3d = e3 - 63;   // region3 for e3: s in [e3-63, e3-35], s%4==0

    const float NEG = -3.402823466e+38f;
    float m0 = NEG, m1 = NEG, m2 = NEG, m3 = NEG;

    float4* orow = reinterpret_cast<float4*>(out + (size_t)row * (N * N));

    const int h = row & (H - 1);          // H = 512
    const int b = row >> 9;
    const bool do_mask = (h == 0);
    float4* mrow = reinterpret_cast<float4*>(
        out + (size_t)B * H * N * N + (size_t)b * (N * N));

#define UPDATE_MAX(S)                                   \
    {                                                   \
        const float xs = xr[(S)];                       \
        if ((S) <= e3) m3 = fmaxf(m3, xs);              \
        if ((S) <= e2) m2 = fmaxf(m2, xs);              \
        if ((S) <= e1) m1 = fmaxf(m1, xs);              \
        if ((S) <= e0) m0 = fmaxf(m0, xs);              \
    }

#define EMIT(S, F0, F1, F2, F3)                                         \
    {                                                                   \
        float4 w;                                                       \
        w.x = (F0) ? m0 : 0.0f;                                         \
        w.y = (F1) ? m1 : 0.0f;                                         \
        w.z = (F2) ? m2 : 0.0f;                                         \
        w.w = (F3) ? m3 : 0.0f;                                         \
        __stcs(&orow[(S) * 16 + eg], w);                                \
        if (do_mask) {                                                  \
            float4 mk;                                                  \
            mk.x = (F0) ? 1.0f : 0.0f;                                  \
            mk.y = (F1) ? 1.0f : 0.0f;                                  \
            mk.z = (F2) ? 1.0f : 0.0f;                                  \
            mk.w = (F3) ? 1.0f : 0.0f;                                  \
            __stcs(&mrow[(S) * 16 + eg], mk);                           \
        }                                                               \
    }

    #pragma unroll
    for (int sb = 60; sb >= 0; sb -= 4) {
        // ---- s = sb+3  (s%4==3, odd): region 1 only ----
        {
            const int s = sb + 3;
            UPDATE_MAX(s);
            const bool f0 = (unsigned)(s - r1a) <= 15u;
            const bool f1 = (unsigned)(s - r1b) <= 15u;
            const bool f2 = (unsigned)(s - r1c) <= 15u;
            const bool f3 = (unsigned)(s - r1d) <= 15u;
            EMIT(s, f0, f1, f2, f3);
        }
        // ---- s = sb+2  (s%4==2, even): region 1 + region 2 (e1,e3) ----
        {
            const int s = sb + 2;
            UPDATE_MAX(s);
            const bool f0 = (unsigned)(s - r1a) <= 15u;
            const bool f1 = ((unsigned)(s - r1b) <= 15u) |
                            ((unsigned)(s - r2b) <= 14u);
            const bool f2 = (unsigned)(s - r1c) <= 15u;
            const bool f3 = ((unsigned)(s - r1d) <= 15u) |
                            ((unsigned)(s - r2d) <= 14u);
            EMIT(s, f0, f1, f2, f3);
        }
        // ---- s = sb+1  (s%4==1, odd): region 1 only ----
        {
            const int s = sb + 1;
            UPDATE_MAX(s);
            const bool f0 = (unsigned)(s - r1a) <= 15u;
            const bool f1 = (unsigned)(s - r1b) <= 15u;
            const bool f2 = (unsigned)(s - r1c) <= 15u;
            const bool f3 = (unsigned)(s - r1d) <= 15u;
            EMIT(s, f0, f1, f2, f3);
        }
        // ---- s = sb    (s%4==0, even): region 1 + region 2 (e1,e3) + region 3 (e3) ----
        {
            const int s = sb;
            UPDATE_MAX(s);
            const bool f0 = (unsigned)(s - r1a) <= 15u;
            const bool f1 = ((unsigned)(s - r1b) <= 15u) |
                            ((unsigned)(s - r2b) <= 14u);
            const bool f2 = (unsigned)(s - r1c) <= 15u;
            const bool f3 = ((unsigned)(s - r1d) <= 15u) |
                            ((unsigned)(s - r2d) <= 14u) |
                            ((unsigned)(s - r3d) <= 28u);
            EMIT(s, f0, f1, f2, f3);
        }
    }
#undef UPDATE_MAX
#undef EMIT
}

extern "C" void kernel_launch(void* const* d_in, const int* in_sizes, int n_in,
                              void* d_out, int out_size) {
    const float* x = (const float*)d_in[0];
    float* out = (float*)d_out;

    const int N = 64;
    const int H = 512;
    const int total = in_sizes[0];        // B*H*N
    const int B = total / (H * N);        // 32

    const int rows = B * H;               // 16384
    const int blocks = rows / 16;         // 1024

    sparseprop_kernel<<<blocks, 256>>>(x, out, B, H);
}